// round 11
// baseline (speedup 1.0000x reference)
#include <cuda_runtime.h>
#include <cuda_fp16.h>
#include <cuda_bf16.h>
#include <cstdint>
#include <cstring>

#define NN 100000
#define NE 800000
#define DM 128

typedef unsigned long long u64;

__device__ __forceinline__ uint32_t smem_to_u32(const void* p) {
    uint32_t a;
    asm("{ .reg .u64 t; cvta.to.shared.u64 t, %1; cvt.u32.u64 %0, t; }" : "=r"(a) : "l"(p));
    return a;
}
__device__ __forceinline__ uint32_t h2_to_u32(__half2 h) {
    uint32_t u;
    memcpy(&u, &h, 4);
    return u;
}
__device__ __forceinline__ void ldsm4(uint32_t* r, uint32_t addr) {
    asm volatile("ldmatrix.sync.aligned.m8n8.x4.shared.b16 {%0,%1,%2,%3}, [%4];"
        : "=r"(r[0]), "=r"(r[1]), "=r"(r[2]), "=r"(r[3]) : "r"(addr));
}
__device__ __forceinline__ void mma16816(float* c, const uint32_t* a, const uint32_t* b) {
    asm volatile(
        "mma.sync.aligned.m16n8k16.row.col.f32.f16.f16.f32 "
        "{%0,%1,%2,%3}, {%4,%5,%6,%7}, {%8,%9}, {%0,%1,%2,%3};"
        : "+f"(c[0]), "+f"(c[1]), "+f"(c[2]), "+f"(c[3])
        : "r"(a[0]), "r"(a[1]), "r"(a[2]), "r"(a[3]), "r"(b[0]), "r"(b[1]));
}

// ---------------- scratch (device globals: no cudaMalloc allowed) ----------------
__device__ float  g_deg[NN];
__device__ float  g_dis[NN];
__device__ int    g_cnt[NN];
__device__ int    g_off[NN + 1];
__device__ int    g_cur[NN];
__device__ uint2  g_ew[2 * NE];              // packed (src, w-bits) per directed edge
__device__ __half g_xh[(size_t)NN * DM];     // layer-1 gather table (fp16 nodes)
__device__ __half g_xh2[(size_t)NN * DM];    // layer-1 output / layer-2 gather+residual
__device__ __half g_wt1[DM * DM];            // W1^T fp16, [n][k]
__device__ __half g_wt2[DM * DM];            // W2^T fp16, [n][k]

#define SCB 256
#define SNB ((NN + SCB - 1) / SCB)   // 391 scan blocks
__device__ int g_bsum[SNB];
__device__ int g_boff[SNB];

// ---------------- build kernels ----------------
__global__ void k_zero() {
    int i = blockIdx.x * blockDim.x + threadIdx.x;
    if (i < NN) { g_deg[i] = 0.f; g_cnt[i] = 0; }
}

__global__ void k_deg(const int* __restrict__ s, const int* __restrict__ r,
                      const float* __restrict__ e) {
    int i = blockIdx.x * blockDim.x + threadIdx.x;
    if (i < NE) {
        int a = s[i], b = r[i];
        float ev = e[i];
        atomicAdd(&g_deg[a], ev);
        atomicAdd(&g_deg[b], ev);
        atomicAdd(&g_cnt[a], 1);
        atomicAdd(&g_cnt[b], 1);
    }
}

// scan1 also computes dis
__global__ void k_scan1() {
    __shared__ int sh[SCB];
    int i = blockIdx.x * SCB + threadIdx.x;
    int v = 0;
    if (i < NN) {
        v = g_cnt[i];
        float d = g_deg[i];
        g_dis[i] = (d > 0.f) ? rsqrtf(d) : 0.f;
    }
    sh[threadIdx.x] = v;
    __syncthreads();
    for (int d = SCB / 2; d > 0; d >>= 1) {
        if (threadIdx.x < d) sh[threadIdx.x] += sh[threadIdx.x + d];
        __syncthreads();
    }
    if (threadIdx.x == 0) g_bsum[blockIdx.x] = sh[0];
}

__global__ void k_scan2() {
    __shared__ int sh[512];
    int t = threadIdx.x;
    int v = (t < SNB) ? g_bsum[t] : 0;
    sh[t] = v;
    __syncthreads();
    for (int d = 1; d < 512; d <<= 1) {
        int x = 0;
        if (t >= d) x = sh[t - d];
        __syncthreads();
        sh[t] += x;
        __syncthreads();
    }
    if (t < SNB) g_boff[t] = sh[t] - v;
    if (t == SNB - 1) g_off[NN] = sh[t];
}

__global__ void k_scan3() {
    __shared__ int sh[SCB];
    int i = blockIdx.x * SCB + threadIdx.x;
    int t = threadIdx.x;
    int v = (i < NN) ? g_cnt[i] : 0;
    sh[t] = v;
    __syncthreads();
    for (int d = 1; d < SCB; d <<= 1) {
        int x = 0;
        if (t >= d) x = sh[t - d];
        __syncthreads();
        sh[t] += x;
        __syncthreads();
    }
    if (i < NN) {
        int excl = sh[t] - v + g_boff[blockIdx.x];
        g_off[i] = excl;
        g_cur[i] = excl;
    }
}

__global__ void k_fill(const int* __restrict__ s, const int* __restrict__ r,
                       const float* __restrict__ e) {
    int i = blockIdx.x * blockDim.x + threadIdx.x;
    if (i < NE) {
        int a = s[i], b = r[i];
        float w = g_dis[a] * e[i] * g_dis[b];
        uint32_t wb = __float_as_uint(w);
        int p = atomicAdd(&g_cur[b], 1);
        g_ew[p] = make_uint2((uint32_t)a, wb);
        int q = atomicAdd(&g_cur[a], 1);
        g_ew[q] = make_uint2((uint32_t)b, wb);
    }
}

// ---------------- prep: nodes->fp16 + W1^T,W2^T->fp16, one launch ----------------
__global__ void k_prep(const float* __restrict__ x, const float* __restrict__ W1,
                       const float* __restrict__ W2) {
    int b = blockIdx.x;
    if (b < 64) {
        int i = b * 256 + threadIdx.x;       // 0..16383
        int n = i & 127, k = i >> 7;
        g_wt1[n * DM + k] = __float2half_rn(__ldg(&W1[i]));
        g_wt2[n * DM + k] = __float2half_rn(__ldg(&W2[i]));
    } else {
        int i = (b - 64) * 256 + threadIdx.x;
        const int N4 = NN * DM / 4;
        if (i < N4) {
            float4 v = __ldg(&((const float4*)x)[i]);
            ((__half2*)g_xh)[2 * i]     = __floats2half2_rn(v.x, v.y);
            ((__half2*)g_xh)[2 * i + 1] = __floats2half2_rn(v.z, v.w);
        }
    }
}

// ---------------- fused aggregation + HMMA GEMM + epilogue -----------------------
// mode 1: gather g_xh;  A@W1; out_h(g_xh2) = resf(fp32) + A@W1 + b
// mode 2: gather g_xh2; A@W2; out(fp32)    = g_xh2      + A@W2 + b
// 128x128 tile per CTA, 8 warps; warp w gathers+owns rows [16w,16w+16).
#define SAW 136

__device__ __forceinline__ void acc_edge(float4& acc, float w, uint2 u) {
    __half2 h0 = *(__half2*)&u.x;
    __half2 h1 = *(__half2*)&u.y;
    float2 f0 = __half22float2(h0);
    float2 f1 = __half22float2(h1);
    acc.x = fmaf(w, f0.x, acc.x);
    acc.y = fmaf(w, f0.y, acc.y);
    acc.z = fmaf(w, f1.x, acc.z);
    acc.w = fmaf(w, f1.y, acc.w);
}

__global__ void __launch_bounds__(256)
k_fused(const float* __restrict__ bias, const float* __restrict__ resf,
        float* __restrict__ out, int mode) {
    extern __shared__ __half sh[];
    __half* sA = sh;                         // [128][SAW]
    __half* sB = sh + 128 * SAW;             // [128][SAW]  (W^T: [n][k])
    float* sBias = (float*)(sh + 2 * 128 * SAW);

    int tid = threadIdx.x;
    int w = tid >> 5, l = tid & 31;
    int rowBase = blockIdx.x * 128;

    if (tid < 128) sBias[tid] = __ldg(&bias[tid]);

    // load B = W^T [n][k] for this layer
    {
        const __half2* wt = (const __half2*)((mode == 1) ? g_wt1 : g_wt2);
#pragma unroll
        for (int i = 0; i < 32; i++) {
            int idx = tid + i * 256;
            int n = idx >> 6;
            int kk = idx & 63;
            *(__half2*)&sB[n * SAW + kk * 2] = __ldg(&wt[idx]);
        }
    }

    // ---- gather phase: warp w aggregates its 16 rows straight into sA ----
    const uint2* __restrict__ xh2 =
        (const uint2*)((mode == 1) ? g_xh : g_xh2);   // row = 32 uint2
#pragma unroll 1
    for (int i = 0; i < 16; i++) {
        int row = 16 * w + i;
        int grow = rowBase + row;
        float4 acc = make_float4(0.f, 0.f, 0.f, 0.f);
        if (grow < NN) {
            int beg = g_off[grow], end = g_off[grow + 1];
            int j = beg;
            for (; j + 4 <= end; j += 4) {
                uint2 e0 = __ldg(&g_ew[j + 0]);
                uint2 e1 = __ldg(&g_ew[j + 1]);
                uint2 e2 = __ldg(&g_ew[j + 2]);
                uint2 e3 = __ldg(&g_ew[j + 3]);
                uint2 u0 = __ldg(&xh2[(size_t)e0.x * 32 + l]);
                uint2 u1 = __ldg(&xh2[(size_t)e1.x * 32 + l]);
                uint2 u2 = __ldg(&xh2[(size_t)e2.x * 32 + l]);
                uint2 u3 = __ldg(&xh2[(size_t)e3.x * 32 + l]);
                acc_edge(acc, __uint_as_float(e0.y), u0);
                acc_edge(acc, __uint_as_float(e1.y), u1);
                acc_edge(acc, __uint_as_float(e2.y), u2);
                acc_edge(acc, __uint_as_float(e3.y), u3);
            }
            if (j < end) {
                int rem = end - j;
                uint2 ez = make_uint2(0u, 0u);
                uint2 e0 = (rem > 0) ? __ldg(&g_ew[j + 0]) : ez;
                uint2 e1 = (rem > 1) ? __ldg(&g_ew[j + 1]) : ez;
                uint2 e2 = (rem > 2) ? __ldg(&g_ew[j + 2]) : ez;
                uint2 z = make_uint2(0u, 0u);
                uint2 u0 = (rem > 0) ? __ldg(&xh2[(size_t)e0.x * 32 + l]) : z;
                uint2 u1 = (rem > 1) ? __ldg(&xh2[(size_t)e1.x * 32 + l]) : z;
                uint2 u2 = (rem > 2) ? __ldg(&xh2[(size_t)e2.x * 32 + l]) : z;
                acc_edge(acc, (rem > 0) ? __uint_as_float(e0.y) : 0.f, u0);
                acc_edge(acc, (rem > 1) ? __uint_as_float(e1.y) : 0.f, u1);
                acc_edge(acc, (rem > 2) ? __uint_as_float(e2.y) : 0.f, u2);
            }
        }
        uint2 hv;
        hv.x = h2_to_u32(__floats2half2_rn(acc.x, acc.y));
        hv.y = h2_to_u32(__floats2half2_rn(acc.z, acc.w));
        *(uint2*)&sA[row * SAW + l * 4] = hv;
    }
    __syncthreads();

    // ---- MMA phase ----
    uint32_t aBase = smem_to_u32(sA);
    uint32_t bBase = smem_to_u32(sB);

    float acc[16][4];
#pragma unroll
    for (int i = 0; i < 16; i++)
#pragma unroll
        for (int jj = 0; jj < 4; jj++) acc[i][jj] = 0.f;

    int aRow = 16 * w + (l & 15);
    int aKsub = (l >> 4) * 8;
    int bNsub = ((l >> 4) & 1) * 8 + (l & 7);
    int bKsub = ((l >> 3) & 1) * 8;

#pragma unroll
    for (int s = 0; s < 8; s++) {
        uint32_t a[4];
        ldsm4(a, aBase + ((aRow * SAW + s * 16 + aKsub) << 1));
#pragma unroll
        for (int ntp = 0; ntp < 8; ntp++) {
            uint32_t b[4];
            int n = 16 * ntp + bNsub;
            ldsm4(b, bBase + ((n * SAW + s * 16 + bKsub) << 1));
            mma16816(acc[2 * ntp + 0], a, b);
            mma16816(acc[2 * ntp + 1], a, b + 2);
        }
    }

    // ---- epilogue ----
    int group = l >> 2, tg = l & 3;
#pragma unroll
    for (int hh = 0; hh < 2; hh++) {
        int grow = rowBase + 16 * w + group + hh * 8;
        if (grow < NN) {
            if (mode == 1) {
                const float* rp = &resf[(size_t)grow * DM];
                __half* hp = &g_xh2[(size_t)grow * DM];
#pragma unroll
                for (int nt = 0; nt < 16; nt++) {
                    int c = 8 * nt + 2 * tg;
                    float2 rv = *(const float2*)&rp[c];
                    float o0 = rv.x + acc[nt][hh * 2 + 0] + sBias[c];
                    float o1 = rv.y + acc[nt][hh * 2 + 1] + sBias[c + 1];
                    *(uint32_t*)&hp[c] = h2_to_u32(__floats2half2_rn(o0, o1));
                }
            } else {
                const __half* rh = &g_xh2[(size_t)grow * DM];
                float* op = &out[(size_t)grow * DM];
#pragma unroll
                for (int nt = 0; nt < 16; nt++) {
                    int c = 8 * nt + 2 * tg;
                    __half2 rv2 = *(const __half2*)&rh[c];
                    float2 rv = __half22float2(rv2);
                    float o0 = rv.x + acc[nt][hh * 2 + 0] + sBias[c];
                    float o1 = rv.y + acc[nt][hh * 2 + 1] + sBias[c + 1];
                    *(float2*)&op[c] = make_float2(o0, o1);
                }
            }
        }
    }
}

// ---------------- launch ----------------
extern "C" void kernel_launch(void* const* d_in, const int* in_sizes, int n_in,
                              void* d_out, int out_size) {
    const float* nodes     = (const float*)d_in[0];
    const int*   senders   = (const int*)d_in[1];
    const int*   receivers = (const int*)d_in[2];
    const float* edges     = (const float*)d_in[3];
    const float* W1 = (const float*)d_in[4];
    const float* b1 = (const float*)d_in[5];
    const float* W2 = (const float*)d_in[6];
    const float* b2 = (const float*)d_in[7];
    float* out = (float*)d_out;

    const size_t SMEM_GEMM = 2 * 128 * SAW * sizeof(__half) + DM * sizeof(float);
    cudaFuncSetAttribute(k_fused, cudaFuncAttributeMaxDynamicSharedMemorySize,
                         (int)SMEM_GEMM);

    const int T = 256;
    // CSR + degree build (shared by both layers)
    k_zero<<<(NN + T - 1) / T, T>>>();
    k_deg<<<(NE + T - 1) / T, T>>>(senders, receivers, edges);
    k_scan1<<<SNB, SCB>>>();           // also computes g_dis
    k_scan2<<<1, 512>>>();
    k_scan3<<<SNB, SCB>>>();
    k_fill<<<(NE + T - 1) / T, T>>>(senders, receivers, edges);

    const int GEMM_GRID = (NN + 127) / 128;            // 782 tiles
    const int PREP_GRID = 64 + (NN * DM / 4 + T - 1) / T;

    k_prep<<<PREP_GRID, T>>>(nodes, W1, W2);

    // layer 1: gather g_xh -> g_xh2 (fp16)
    k_fused<<<GEMM_GRID, T, SMEM_GEMM>>>(b1, nodes, nullptr, 1);
    // layer 2: gather g_xh2 -> out (fp32)
    k_fused<<<GEMM_GRID, T, SMEM_GEMM>>>(b2, nullptr, out, 2);
}

// round 12
// speedup vs baseline: 1.2966x; 1.2966x over previous
#include <cuda_runtime.h>
#include <cuda_fp16.h>
#include <cuda_bf16.h>
#include <cstdint>
#include <cstring>

#define NN 100000
#define NE 800000
#define DM 128

typedef unsigned long long u64;

__device__ __forceinline__ uint32_t smem_to_u32(const void* p) {
    uint32_t a;
    asm("{ .reg .u64 t; cvta.to.shared.u64 t, %1; cvt.u32.u64 %0, t; }" : "=r"(a) : "l"(p));
    return a;
}
__device__ __forceinline__ uint32_t h2_to_u32(__half2 h) {
    uint32_t u;
    memcpy(&u, &h, 4);
    return u;
}
__device__ __forceinline__ void ldsm4(uint32_t* r, uint32_t addr) {
    asm volatile("ldmatrix.sync.aligned.m8n8.x4.shared.b16 {%0,%1,%2,%3}, [%4];"
        : "=r"(r[0]), "=r"(r[1]), "=r"(r[2]), "=r"(r[3]) : "r"(addr));
}
__device__ __forceinline__ void mma16816(float* c, const uint32_t* a, const uint32_t* b) {
    asm volatile(
        "mma.sync.aligned.m16n8k16.row.col.f32.f16.f16.f32 "
        "{%0,%1,%2,%3}, {%4,%5,%6,%7}, {%8,%9}, {%0,%1,%2,%3};"
        : "+f"(c[0]), "+f"(c[1]), "+f"(c[2]), "+f"(c[3])
        : "r"(a[0]), "r"(a[1]), "r"(a[2]), "r"(a[3]), "r"(b[0]), "r"(b[1]));
}

// ---------------- scratch (device globals: no cudaMalloc allowed) ----------------
__device__ float  g_deg[NN];
__device__ float  g_dis[NN];
__device__ int    g_cnt[NN];
__device__ int    g_off[NN + 1];
__device__ int    g_cur[NN];
__device__ uint2  g_ew[2 * NE];              // packed (src, w-bits) per directed edge
__device__ __half g_aggh[(size_t)NN * DM];   // aggregation result, fp16 (A of GEMM)
__device__ __half g_xh[(size_t)NN * DM];     // fp16 node table (gather + L1 residual)
__device__ __half g_xh2[(size_t)NN * DM];    // L1 output (L2 gather + residual)
__device__ __half g_wt1[DM * DM];            // W1^T fp16, [n][k]
__device__ __half g_wt2[DM * DM];            // W2^T fp16, [n][k]

#define SCB 256
#define SNB ((NN + SCB - 1) / SCB)   // 391 scan blocks
__device__ int g_bsum[SNB];
__device__ int g_boff[SNB];

// ---------------- prep: zero counters + nodes->fp16 + W^T->fp16 ------------------
__global__ void k_prep(const float* __restrict__ x, const float* __restrict__ W1,
                       const float* __restrict__ W2) {
    int b = blockIdx.x;
    if (b < 64) {
        int i = b * 256 + threadIdx.x;       // 0..16383
        int n = i & 127, k = i >> 7;
        g_wt1[n * DM + k] = __float2half_rn(__ldg(&W1[i]));
        g_wt2[n * DM + k] = __float2half_rn(__ldg(&W2[i]));
    } else if (b < 64 + SNB) {
        int i = (b - 64) * 256 + threadIdx.x;
        if (i < NN) { g_deg[i] = 0.f; g_cnt[i] = 0; }
    } else {
        int i = (b - 64 - SNB) * 256 + threadIdx.x;
        const int N4 = NN * DM / 4;
        if (i < N4) {
            float4 v = __ldg(&((const float4*)x)[i]);
            ((__half2*)g_xh)[2 * i]     = __floats2half2_rn(v.x, v.y);
            ((__half2*)g_xh)[2 * i + 1] = __floats2half2_rn(v.z, v.w);
        }
    }
}

// ---------------- build kernels ----------------
__global__ void k_deg(const int* __restrict__ s, const int* __restrict__ r,
                      const float* __restrict__ e) {
    int i = blockIdx.x * blockDim.x + threadIdx.x;
    if (i < NE) {
        int a = s[i], b = r[i];
        float ev = e[i];
        atomicAdd(&g_deg[a], ev);
        atomicAdd(&g_deg[b], ev);
        atomicAdd(&g_cnt[a], 1);
        atomicAdd(&g_cnt[b], 1);
    }
}

// scan1 also computes dis
__global__ void k_scan1() {
    __shared__ int sh[SCB];
    int i = blockIdx.x * SCB + threadIdx.x;
    int v = 0;
    if (i < NN) {
        v = g_cnt[i];
        float d = g_deg[i];
        g_dis[i] = (d > 0.f) ? rsqrtf(d) : 0.f;
    }
    sh[threadIdx.x] = v;
    __syncthreads();
    for (int d = SCB / 2; d > 0; d >>= 1) {
        if (threadIdx.x < d) sh[threadIdx.x] += sh[threadIdx.x + d];
        __syncthreads();
    }
    if (threadIdx.x == 0) g_bsum[blockIdx.x] = sh[0];
}

__global__ void k_scan2() {
    __shared__ int sh[512];
    int t = threadIdx.x;
    int v = (t < SNB) ? g_bsum[t] : 0;
    sh[t] = v;
    __syncthreads();
    for (int d = 1; d < 512; d <<= 1) {
        int x = 0;
        if (t >= d) x = sh[t - d];
        __syncthreads();
        sh[t] += x;
        __syncthreads();
    }
    if (t < SNB) g_boff[t] = sh[t] - v;
    if (t == SNB - 1) g_off[NN] = sh[t];
}

__global__ void k_scan3() {
    __shared__ int sh[SCB];
    int i = blockIdx.x * SCB + threadIdx.x;
    int t = threadIdx.x;
    int v = (i < NN) ? g_cnt[i] : 0;
    sh[t] = v;
    __syncthreads();
    for (int d = 1; d < SCB; d <<= 1) {
        int x = 0;
        if (t >= d) x = sh[t - d];
        __syncthreads();
        sh[t] += x;
        __syncthreads();
    }
    if (i < NN) {
        int excl = sh[t] - v + g_boff[blockIdx.x];
        g_off[i] = excl;
        g_cur[i] = excl;
    }
}

__global__ void k_fill(const int* __restrict__ s, const int* __restrict__ r,
                       const float* __restrict__ e) {
    int i = blockIdx.x * blockDim.x + threadIdx.x;
    if (i < NE) {
        int a = s[i], b = r[i];
        float w = g_dis[a] * e[i] * g_dis[b];
        uint32_t wb = __float_as_uint(w);
        int p = atomicAdd(&g_cur[b], 1);
        g_ew[p] = make_uint2((uint32_t)a, wb);
        int q = atomicAdd(&g_cur[a], 1);
        g_ew[q] = make_uint2((uint32_t)b, wb);
    }
}

// ---------------- aggregation: one warp per node, fp16 gather, MLP=8 -------------
__device__ __forceinline__ void acc_edge(float4& acc, float w, uint2 u) {
    __half2 h0 = *(__half2*)&u.x;
    __half2 h1 = *(__half2*)&u.y;
    float2 f0 = __half22float2(h0);
    float2 f1 = __half22float2(h1);
    acc.x = fmaf(w, f0.x, acc.x);
    acc.y = fmaf(w, f0.y, acc.y);
    acc.z = fmaf(w, f1.x, acc.z);
    acc.w = fmaf(w, f1.y, acc.w);
}

__global__ void k_agg(int layer) {
    int warp = (blockIdx.x * blockDim.x + threadIdx.x) >> 5;
    int lane = threadIdx.x & 31;
    if (warp >= NN) return;
    int beg = g_off[warp], end = g_off[warp + 1];
    float4 acc = make_float4(0.f, 0.f, 0.f, 0.f);
    const uint2* __restrict__ xh2 =
        (const uint2*)((layer == 1) ? g_xh : g_xh2);

    int j = beg;
    // 8 edges per iteration -> 8 gathers in flight
    for (; j + 8 <= end; j += 8) {
        uint2 e[8], u[8];
#pragma unroll
        for (int q = 0; q < 8; q++) e[q] = __ldg(&g_ew[j + q]);
#pragma unroll
        for (int q = 0; q < 8; q++) u[q] = __ldg(&xh2[(size_t)e[q].x * 32 + lane]);
#pragma unroll
        for (int q = 0; q < 8; q++) acc_edge(acc, __uint_as_float(e[q].y), u[q]);
    }
    if (j < end) {
        int rem = end - j;   // 1..7
        uint2 e[7], u[7];
        const uint2 z = make_uint2(0u, 0u);
#pragma unroll
        for (int q = 0; q < 7; q++) e[q] = (q < rem) ? __ldg(&g_ew[j + q]) : z;
#pragma unroll
        for (int q = 0; q < 7; q++)
            u[q] = (q < rem) ? __ldg(&xh2[(size_t)e[q].x * 32 + lane]) : z;
#pragma unroll
        for (int q = 0; q < 7; q++)
            acc_edge(acc, (q < rem) ? __uint_as_float(e[q].y) : 0.f, u[q]);
    }
    // write fp16 (A operand of the HMMA GEMM)
    uint2 hv;
    hv.x = h2_to_u32(__floats2half2_rn(acc.x, acc.y));
    hv.y = h2_to_u32(__floats2half2_rn(acc.z, acc.w));
    ((uint2*)g_aggh)[(size_t)warp * 32 + lane] = hv;
}

// ---------------- HMMA GEMM ------------------------------------------------------
// mode 1 (layer 1): g_xh2(fp16) = g_xh(fp16 residual) + A@W1 + b
// mode 2 (layer 2): out(fp32)   = g_xh2(fp16 residual) + A@W2 + b
// 128x128 tile per CTA, 8 warps; warp w -> rows [16w,16w+16), all 128 cols.
#define SAW 136

__global__ void __launch_bounds__(256)
k_gemm_mma(const float* __restrict__ bias, float* __restrict__ out, int mode) {
    extern __shared__ __half sh[];
    __half* sA = sh;                         // [128][SAW]
    __half* sB = sh + 128 * SAW;             // [128][SAW]  (W^T: [n][k])
    float* sBias = (float*)(sh + 2 * 128 * SAW);

    int tid = threadIdx.x;
    int w = tid >> 5, l = tid & 31;
    int rowBase = blockIdx.x * 128;

    if (tid < 128) sBias[tid] = __ldg(&bias[tid]);

    // load A tile from g_aggh (128 rows x 64 half2)
    const __half2* ag = (const __half2*)g_aggh;
#pragma unroll
    for (int i = 0; i < 32; i++) {
        int idx = tid + i * 256;             // 0..8191
        int row = idx >> 6;
        int kk = idx & 63;                   // half2 index along k
        int grow = rowBase + row;
        __half2 v = (grow < NN) ? __ldg(&ag[(size_t)grow * 64 + kk])
                                : __float2half2_rn(0.f);
        *(__half2*)&sA[row * SAW + kk * 2] = v;
    }
    // load B = W^T [n][k]
    {
        const __half2* wt = (const __half2*)((mode == 1) ? g_wt1 : g_wt2);
#pragma unroll
        for (int i = 0; i < 32; i++) {
            int idx = tid + i * 256;
            int n = idx >> 6;
            int kk = idx & 63;
            *(__half2*)&sB[n * SAW + kk * 2] = __ldg(&wt[idx]);
        }
    }
    __syncthreads();

    uint32_t aBase = smem_to_u32(sA);
    uint32_t bBase = smem_to_u32(sB);

    float acc[16][4];
#pragma unroll
    for (int i = 0; i < 16; i++)
#pragma unroll
        for (int jj = 0; jj < 4; jj++) acc[i][jj] = 0.f;

    int aRow = 16 * w + (l & 15);
    int aKsub = (l >> 4) * 8;
    int bNsub = ((l >> 4) & 1) * 8 + (l & 7);
    int bKsub = ((l >> 3) & 1) * 8;

#pragma unroll
    for (int s = 0; s < 8; s++) {
        uint32_t a[4];
        ldsm4(a, aBase + ((aRow * SAW + s * 16 + aKsub) << 1));
#pragma unroll
        for (int ntp = 0; ntp < 8; ntp++) {
            uint32_t b[4];
            int n = 16 * ntp + bNsub;
            ldsm4(b, bBase + ((n * SAW + s * 16 + bKsub) << 1));
            mma16816(acc[2 * ntp + 0], a, b);
            mma16816(acc[2 * ntp + 1], a, b + 2);
        }
    }

    // epilogue: fp16 residual (g_xh for L1, g_xh2 for L2) + bias
    const __half* rtab = (mode == 1) ? g_xh : g_xh2;
    int group = l >> 2, tg = l & 3;
#pragma unroll
    for (int hh = 0; hh < 2; hh++) {
        int grow = rowBase + 16 * w + group + hh * 8;
        if (grow < NN) {
            const __half* rh = &rtab[(size_t)grow * DM];
            if (mode == 1) {
                __half* hp = &g_xh2[(size_t)grow * DM];
#pragma unroll
                for (int nt = 0; nt < 16; nt++) {
                    int c = 8 * nt + 2 * tg;
                    float2 rv = __half22float2(*(const __half2*)&rh[c]);
                    float o0 = rv.x + acc[nt][hh * 2 + 0] + sBias[c];
                    float o1 = rv.y + acc[nt][hh * 2 + 1] + sBias[c + 1];
                    *(uint32_t*)&hp[c] = h2_to_u32(__floats2half2_rn(o0, o1));
                }
            } else {
                float* op = &out[(size_t)grow * DM];
#pragma unroll
                for (int nt = 0; nt < 16; nt++) {
                    int c = 8 * nt + 2 * tg;
                    float2 rv = __half22float2(*(const __half2*)&rh[c]);
                    float o0 = rv.x + acc[nt][hh * 2 + 0] + sBias[c];
                    float o1 = rv.y + acc[nt][hh * 2 + 1] + sBias[c + 1];
                    *(float2*)&op[c] = make_float2(o0, o1);
                }
            }
        }
    }
}

// ---------------- launch ----------------
extern "C" void kernel_launch(void* const* d_in, const int* in_sizes, int n_in,
                              void* d_out, int out_size) {
    const float* nodes     = (const float*)d_in[0];
    const int*   senders   = (const int*)d_in[1];
    const int*   receivers = (const int*)d_in[2];
    const float* edges     = (const float*)d_in[3];
    const float* W1 = (const float*)d_in[4];
    const float* b1 = (const float*)d_in[5];
    const float* W2 = (const float*)d_in[6];
    const float* b2 = (const float*)d_in[7];
    float* out = (float*)d_out;

    const size_t SMEM_GEMM = 2 * 128 * SAW * sizeof(__half) + DM * sizeof(float);
    cudaFuncSetAttribute(k_gemm_mma, cudaFuncAttributeMaxDynamicSharedMemorySize,
                         (int)SMEM_GEMM);

    const int T = 256;
    const int PREP_GRID = 64 + SNB + (NN * DM / 4 + T - 1) / T;

    // prep (zero counters + fp16 conversions) then CSR build
    k_prep<<<PREP_GRID, T>>>(nodes, W1, W2);
    k_deg<<<(NE + T - 1) / T, T>>>(senders, receivers, edges);
    k_scan1<<<SNB, SCB>>>();           // also computes g_dis
    k_scan2<<<1, 512>>>();
    k_scan3<<<SNB, SCB>>>();
    k_fill<<<(NE + T - 1) / T, T>>>(senders, receivers, edges);

    const int AGG_GRID  = (NN * 32 + T - 1) / T;       // one warp per node
    const int GEMM_GRID = (NN + 127) / 128;            // 782 tiles

    // layer 1: gather g_xh -> g_xh2 (fp16)
    k_agg<<<AGG_GRID, T>>>(1);
    k_gemm_mma<<<GEMM_GRID, T, SMEM_GEMM>>>(b1, nullptr, 1);
    // layer 2: gather g_xh2 -> out (fp32)
    k_agg<<<AGG_GRID, T>>>(2);
    k_gemm_mma<<<GEMM_GRID, T, SMEM_GEMM>>>(b2, out, 2);
}